// round 1
// baseline (speedup 1.0000x reference)
#include <cuda_runtime.h>
#include <math.h>

#define NREQ   100000
#define NCODE  100000
#define CC     256
#define HEADS  8
#define NE     500000
#define NLAB   200000

// ---------------- scratch (device globals; no allocations allowed) ----------
__device__ __align__(128) float g_h_req  [(size_t)NREQ  * CC];
__device__ __align__(128) float g_h_code [(size_t)NCODE * CC];
__device__ __align__(128) float g_acc_req [(size_t)NREQ  * CC];
__device__ __align__(128) float g_acc_code[(size_t)NCODE * CC];
__device__ __align__(128) float g_as_rc[NREQ  * HEADS];
__device__ __align__(128) float g_ad_rc[NCODE * HEADS];
__device__ __align__(128) float g_as_cr[NCODE * HEADS];
__device__ __align__(128) float g_ad_cr[NREQ  * HEADS];
__device__ __align__(128) float g_s_req [NREQ  * HEADS];
__device__ __align__(128) float g_s_code[NCODE * HEADS];
__device__ __align__(128) float g_bnsum[1024];   // [which*512 + {sum[256], sumsq[256]}]
__device__ __align__(128) float g_bn[1024];      // [which*512 + {scale[256], shift[256]}]

// ---------------- small asm helpers ----------------------------------------
__device__ __forceinline__ void ffma2(unsigned long long &d, unsigned long long a,
                                      unsigned long long b) {
    asm("fma.rn.f32x2 %0, %1, %2, %0;" : "+l"(d) : "l"(a), "l"(b));
}
__device__ __forceinline__ unsigned long long pk2(float x, float y) {
    unsigned long long r;
    asm("mov.b64 %0, {%1,%2};" : "=l"(r) : "f"(x), "f"(y));
    return r;
}
__device__ __forceinline__ float2 upk2(unsigned long long v) {
    float2 r;
    asm("mov.b64 {%0,%1}, %2;" : "=f"(r.x), "=f"(r.y) : "l"(v));
    return r;
}
__device__ __forceinline__ void red4(float* p, float4 v) {
    asm volatile("red.global.add.v4.f32 [%0], {%1,%2,%3,%4};"
                 :: "l"(p), "f"(v.x), "f"(v.y), "f"(v.z), "f"(v.w) : "memory");
}

// ---------------- zero fill --------------------------------------------------
__global__ __launch_bounds__(256) void k_zero(float4* p, int n4) {
    int i = blockIdx.x * 256 + threadIdx.x;
    if (i < n4) p[i] = make_float4(0.f, 0.f, 0.f, 0.f);
}

// ---------------- GEMM: C[m,o] = sum_k A[m,k]*W[o,k] + b[o] ------------------
#define BM 64
#define BN 64
#define BK 16
__global__ __launch_bounds__(256) void k_gemm(
    const float* __restrict__ A, const float* __restrict__ W,
    const float* __restrict__ bias, float* __restrict__ Cmat, int M)
{
    __shared__ float As[BK][BM + 4];
    __shared__ float Bs[BK][BN + 4];
    const int t  = threadIdx.x;
    const int bm = blockIdx.x * BM;
    const int bn = blockIdx.y * BN;
    const int tx = t & 15, ty = t >> 4;

    unsigned long long acc[4][2];
#pragma unroll
    for (int i = 0; i < 4; i++) { acc[i][0] = 0ull; acc[i][1] = 0ull; }

    const int lm = t >> 2;
    const int lk = (t & 3) << 2;
    const bool aok = (bm + lm) < M;
    const float* Ap = A + (size_t)(bm + lm) * CC + lk;
    const float* Wp = W + (size_t)(bn + lm) * CC + lk;

    for (int k0 = 0; k0 < CC; k0 += BK) {
        float4 av = aok ? *(const float4*)(Ap + k0) : make_float4(0.f, 0.f, 0.f, 0.f);
        float4 wv = *(const float4*)(Wp + k0);
        __syncthreads();
        As[lk + 0][lm] = av.x; As[lk + 1][lm] = av.y;
        As[lk + 2][lm] = av.z; As[lk + 3][lm] = av.w;
        Bs[lk + 0][lm] = wv.x; Bs[lk + 1][lm] = wv.y;
        Bs[lk + 2][lm] = wv.z; Bs[lk + 3][lm] = wv.w;
        __syncthreads();
#pragma unroll
        for (int kk = 0; kk < BK; kk++) {
            float4 a = *(const float4*)&As[kk][ty << 2];
            float4 b = *(const float4*)&Bs[kk][tx << 2];
            unsigned long long b01 = pk2(b.x, b.y), b23 = pk2(b.z, b.w);
            unsigned long long d;
            d = pk2(a.x, a.x); ffma2(acc[0][0], d, b01); ffma2(acc[0][1], d, b23);
            d = pk2(a.y, a.y); ffma2(acc[1][0], d, b01); ffma2(acc[1][1], d, b23);
            d = pk2(a.z, a.z); ffma2(acc[2][0], d, b01); ffma2(acc[2][1], d, b23);
            d = pk2(a.w, a.w); ffma2(acc[3][0], d, b01); ffma2(acc[3][1], d, b23);
        }
    }
    float4 bv = *(const float4*)(bias + bn + (tx << 2));
#pragma unroll
    for (int i = 0; i < 4; i++) {
        int m = bm + (ty << 2) + i;
        if (m < M) {
            float2 lo = upk2(acc[i][0]);
            float2 hi = upk2(acc[i][1]);
            float4 o = make_float4(lo.x + bv.x, lo.y + bv.y, hi.x + bv.z, hi.y + bv.w);
            *(float4*)(Cmat + (size_t)m * CC + bn + (tx << 2)) = o;
        }
    }
}

// ---------------- per-node attention dots -----------------------------------
// outA[n,h] = sum_d h[n,h,d]*attA[h,d];  outB same with attB. warp per node.
__global__ __launch_bounds__(256) void k_attdot(
    const float* __restrict__ h, const float* __restrict__ attA,
    const float* __restrict__ attB, float* __restrict__ outA,
    float* __restrict__ outB, int N)
{
    __shared__ float sA[256], sB[256];
    int t = threadIdx.x;
    sA[t] = attA[t];
    sB[t] = attB[t];
    __syncthreads();
    int node = blockIdx.x * 8 + (t >> 5);
    int lane = t & 31;
    if (node >= N) return;
    const float4* row = (const float4*)(h + (size_t)node * CC);
    float4 v0 = row[lane];        // channels 4*lane..      (head lane>>3)
    float4 v1 = row[lane + 32];   // channels 128+4*lane..  (head 4+(lane>>3))
    int c0 = 4 * lane, c1 = 128 + 4 * lane;
    float pA0 = v0.x * sA[c0] + v0.y * sA[c0 + 1] + v0.z * sA[c0 + 2] + v0.w * sA[c0 + 3];
    float pA1 = v1.x * sA[c1] + v1.y * sA[c1 + 1] + v1.z * sA[c1 + 2] + v1.w * sA[c1 + 3];
    float pB0 = v0.x * sB[c0] + v0.y * sB[c0 + 1] + v0.z * sB[c0 + 2] + v0.w * sB[c0 + 3];
    float pB1 = v1.x * sB[c1] + v1.y * sB[c1 + 1] + v1.z * sB[c1 + 2] + v1.w * sB[c1 + 3];
#pragma unroll
    for (int o = 1; o < 8; o <<= 1) {
        pA0 += __shfl_xor_sync(0xffffffffu, pA0, o);
        pA1 += __shfl_xor_sync(0xffffffffu, pA1, o);
        pB0 += __shfl_xor_sync(0xffffffffu, pB0, o);
        pB1 += __shfl_xor_sync(0xffffffffu, pB1, o);
    }
    if ((lane & 7) == 0) {
        int hh = lane >> 3;
        outA[node * 8 + hh]     = pA0;
        outA[node * 8 + 4 + hh] = pA1;
        outB[node * 8 + hh]     = pB0;
        outB[node * 8 + 4 + hh] = pB1;
    }
}

// ---------------- fused edge pass: exp-logit, seg-sum, scatter ---------------
// warp per edge. e[h]=exp(leaky(a_s[src,h]+a_d[dst,h])); s[dst,h]+=e[h];
// acc[dst,:] += e[head(c)] * h_src[src,:]
__global__ __launch_bounds__(256) void k_edge(
    const int* __restrict__ eidx,          // [2,NE]: src row then dst row
    const float* __restrict__ a_s, const float* __restrict__ a_d,
    const float* __restrict__ hsrc,
    float* __restrict__ sdst, float* __restrict__ acc)
{
    int e = blockIdx.x * 8 + (threadIdx.x >> 5);
    int lane = threadIdx.x & 31;
    if (e >= NE) return;
    int src = eidx[e];
    int dst = eidx[NE + e];
    float ev = 0.f;
    if (lane < 8) {
        float l = a_s[src * 8 + lane] + a_d[dst * 8 + lane];
        l = (l > 0.f) ? l : 0.2f * l;
        ev = __expf(l);
        atomicAdd(&sdst[dst * 8 + lane], ev);
    }
    float w0 = __shfl_sync(0xffffffffu, ev, lane >> 3);
    float w1 = __shfl_sync(0xffffffffu, ev, 4 + (lane >> 3));
    const float4* hp = (const float4*)(hsrc + (size_t)src * CC);
    float4 m0 = hp[lane];
    float4 m1 = hp[lane + 32];
    m0.x *= w0; m0.y *= w0; m0.z *= w0; m0.w *= w0;
    m1.x *= w1; m1.y *= w1; m1.z *= w1; m1.w *= w1;
    float* dp = acc + (size_t)dst * CC + 4 * lane;
    red4(dp, m0);
    red4(dp + 128, m1);
}

// ---------------- finalize: divide by seg-sum, relu, BN partial sums ---------
// block = 256 threads; quad q = t&63 (channels 4q..4q+3), rowlane = t>>6;
// each block handles 32 rows.
__global__ __launch_bounds__(256) void k_finalize(
    float* __restrict__ acc, const float* __restrict__ s,
    float* __restrict__ bnsum, int N)
{
    const int q = threadIdx.x & 63;
    const int rl = threadIdx.x >> 6;
    const int row0 = blockIdx.x * 32;
    const int head = q >> 3;
    float4 sum = make_float4(0.f, 0.f, 0.f, 0.f);
    float4 sq  = make_float4(0.f, 0.f, 0.f, 0.f);
#pragma unroll
    for (int i = 0; i < 8; i++) {
        int r = row0 + i * 4 + rl;
        if (r < N) {
            float inv = 1.f / (s[r * 8 + head] + 1e-16f);
            float4 v = *(float4*)(acc + (size_t)r * CC + 4 * q);
            v.x = fmaxf(v.x * inv, 0.f);
            v.y = fmaxf(v.y * inv, 0.f);
            v.z = fmaxf(v.z * inv, 0.f);
            v.w = fmaxf(v.w * inv, 0.f);
            *(float4*)(acc + (size_t)r * CC + 4 * q) = v;
            sum.x += v.x; sum.y += v.y; sum.z += v.z; sum.w += v.w;
            sq.x += v.x * v.x; sq.y += v.y * v.y; sq.z += v.z * v.z; sq.w += v.w * v.w;
        }
    }
    __shared__ float4 shs[256], shq[256];
    shs[threadIdx.x] = sum;
    shq[threadIdx.x] = sq;
    __syncthreads();
    if (threadIdx.x < 64) {
        float4 S = shs[threadIdx.x];
        float4 Q = shq[threadIdx.x];
#pragma unroll
        for (int k = 64; k < 256; k += 64) {
            float4 a = shs[threadIdx.x + k];
            float4 b = shq[threadIdx.x + k];
            S.x += a.x; S.y += a.y; S.z += a.z; S.w += a.w;
            Q.x += b.x; Q.y += b.y; Q.z += b.z; Q.w += b.w;
        }
        int c = 4 * threadIdx.x;
        atomicAdd(&bnsum[c + 0], S.x); atomicAdd(&bnsum[c + 1], S.y);
        atomicAdd(&bnsum[c + 2], S.z); atomicAdd(&bnsum[c + 3], S.w);
        atomicAdd(&bnsum[256 + c + 0], Q.x); atomicAdd(&bnsum[256 + c + 1], Q.y);
        atomicAdd(&bnsum[256 + c + 2], Q.z); atomicAdd(&bnsum[256 + c + 3], Q.w);
    }
}

// ---------------- BN stats -> per-channel affine -----------------------------
__global__ __launch_bounds__(512) void k_bnstats(
    const float* __restrict__ gamma, const float* __restrict__ beta)
{
    int t = threadIdx.x;
    int c = t & 255;
    int which = t >> 8;                 // 0 = req, 1 = code
    const float invN = 1.f / 100000.f;
    float mean = g_bnsum[which * 512 + c] * invN;
    float var  = g_bnsum[which * 512 + 256 + c] * invN - mean * mean;
    float scale = gamma[c] * rsqrtf(var + 1e-5f);
    g_bn[which * 512 + c]       = scale;
    g_bn[which * 512 + 256 + c] = beta[c] - mean * scale;
}

// ---------------- classifier: sigmoid(dot(BN(z_req[i]), BN(z_code[j]))) ------
__global__ __launch_bounds__(256) void k_classify(
    const int* __restrict__ eli, float* __restrict__ out)
{
    __shared__ float bn[1024];
    int t = threadIdx.x;
#pragma unroll
    for (int k = 0; k < 4; k++) bn[t + 256 * k] = g_bn[t + 256 * k];
    __syncthreads();
    int e = blockIdx.x * 8 + (t >> 5);
    int lane = t & 31;
    if (e >= NLAB) return;
    int i = eli[e];
    int j = eli[NLAB + e];
    const float4* zr = (const float4*)(g_acc_req + (size_t)i * CC);
    const float4* zc = (const float4*)(g_acc_code + (size_t)j * CC);
    float4 a0 = zr[lane], a1 = zr[lane + 32];
    float4 b0 = zc[lane], b1 = zc[lane + 32];
    int c0 = 4 * lane, c1 = 128 + 4 * lane;
    float dot = 0.f;
#pragma unroll
    for (int k = 0; k < 4; k++) {
        float av = (&a0.x)[k], bv = (&b0.x)[k];
        float ya = av * bn[c0 + k] + bn[256 + c0 + k];
        float yb = bv * bn[512 + c0 + k] + bn[768 + c0 + k];
        dot += ya * yb;
    }
#pragma unroll
    for (int k = 0; k < 4; k++) {
        float av = (&a1.x)[k], bv = (&b1.x)[k];
        float ya = av * bn[c1 + k] + bn[256 + c1 + k];
        float yb = bv * bn[512 + c1 + k] + bn[768 + c1 + k];
        dot += ya * yb;
    }
#pragma unroll
    for (int o = 16; o >= 1; o >>= 1) dot += __shfl_xor_sync(0xffffffffu, dot, o);
    if (lane == 0) out[e] = 1.f / (1.f + __expf(-dot));
}

// ---------------- host -------------------------------------------------------
template <class T>
static T* getsym(const void* sym) {
    void* p = nullptr;
    cudaGetSymbolAddress(&p, sym);
    return (T*)p;
}

extern "C" void kernel_launch(void* const* d_in, const int* in_sizes, int n_in,
                              void* d_out, int out_size)
{
    const float* x_req      = (const float*)d_in[0];
    const float* x_code     = (const float*)d_in[1];
    const int*   e_rc       = (const int*)d_in[2];
    const int*   e_cr       = (const int*)d_in[3];
    const int*   eli        = (const int*)d_in[4];
    const float* W_req      = (const float*)d_in[5];
    const float* b_req      = (const float*)d_in[6];
    const float* W_code     = (const float*)d_in[7];
    const float* b_code     = (const float*)d_in[8];
    const float* att_src_rc = (const float*)d_in[9];
    const float* att_dst_rc = (const float*)d_in[10];
    const float* att_src_cr = (const float*)d_in[11];
    const float* att_dst_cr = (const float*)d_in[12];
    // d_in[13..15] (k_W, k_b, q) are mathematically dead: semantic attention
    // over a single metapath is identity.
    const float* gamma      = (const float*)d_in[16];
    const float* beta       = (const float*)d_in[17];
    float* out = (float*)d_out;

    float* h_req    = getsym<float>(g_h_req);
    float* h_code   = getsym<float>(g_h_code);
    float* acc_req  = getsym<float>(g_acc_req);
    float* acc_code = getsym<float>(g_acc_code);
    float* as_rc    = getsym<float>(g_as_rc);
    float* ad_rc    = getsym<float>(g_ad_rc);
    float* as_cr    = getsym<float>(g_as_cr);
    float* ad_cr    = getsym<float>(g_ad_cr);
    float* s_req    = getsym<float>(g_s_req);
    float* s_code   = getsym<float>(g_s_code);
    float* bnsum    = getsym<float>(g_bnsum);

    const int accN4 = NREQ * CC / 4;                       // 6.4M float4
    k_zero<<<(accN4 + 255) / 256, 256>>>((float4*)acc_req, accN4);
    k_zero<<<(accN4 + 255) / 256, 256>>>((float4*)acc_code, accN4);
    const int sN4 = NREQ * HEADS / 4;
    k_zero<<<(sN4 + 255) / 256, 256>>>((float4*)s_req, sN4);
    k_zero<<<(sN4 + 255) / 256, 256>>>((float4*)s_code, sN4);
    k_zero<<<1, 256>>>((float4*)bnsum, 256);

    dim3 ggrid((NREQ + BM - 1) / BM, CC / BN);
    k_gemm<<<ggrid, 256>>>(x_req, W_req, b_req, h_req, NREQ);
    k_gemm<<<ggrid, 256>>>(x_code, W_code, b_code, h_code, NCODE);

    k_attdot<<<(NREQ + 7) / 8, 256>>>(h_req, att_src_rc, att_dst_cr, as_rc, ad_cr, NREQ);
    k_attdot<<<(NCODE + 7) / 8, 256>>>(h_code, att_dst_rc, att_src_cr, ad_rc, as_cr, NCODE);

    k_edge<<<(NE + 7) / 8, 256>>>(e_rc, as_rc, ad_rc, h_req, s_code, acc_code);
    k_edge<<<(NE + 7) / 8, 256>>>(e_cr, as_cr, ad_cr, h_code, s_req, acc_req);

    k_finalize<<<NREQ / 32, 256>>>(acc_req, s_req, bnsum, NREQ);
    k_finalize<<<NCODE / 32, 256>>>(acc_code, s_code, bnsum + 512, NCODE);

    k_bnstats<<<1, 512>>>(gamma, beta);

    k_classify<<<(NLAB + 7) / 8, 256>>>(eli, out);
}

// round 5
// speedup vs baseline: 1.5659x; 1.5659x over previous
#include <cuda_runtime.h>
#include <math.h>
#include <cstdint>

#define NNODE  100000
#define CC     256
#define HEADS  8
#define NE     500000
#define NLAB   200000

#define MTILE  128
#define KC     32
#define NCHUNK 8

// ---------------- scratch (device globals; no allocations allowed) ----------
__device__ __align__(128) float g_h_req  [(size_t)NNODE * CC];
__device__ __align__(128) float g_h_code [(size_t)NNODE * CC];
__device__ __align__(128) float g_acc_req [(size_t)NNODE * CC];
__device__ __align__(128) float g_acc_code[(size_t)NNODE * CC];
__device__ __align__(128) float g_as_rc[NNODE * HEADS];
__device__ __align__(128) float g_ad_rc[NNODE * HEADS];
__device__ __align__(128) float g_as_cr[NNODE * HEADS];
__device__ __align__(128) float g_ad_cr[NNODE * HEADS];
__device__ __align__(128) float g_s_req [NNODE * HEADS];
__device__ __align__(128) float g_s_code[NNODE * HEADS];
__device__ __align__(128) float g_bnsum[1024];   // [which*512 + {sum[256], sumsq[256]}]
__device__ __align__(128) float g_bn[1024];      // [which*512 + {scale[256], shift[256]}]

// ---------------- helpers ----------------------------------------------------
__device__ __forceinline__ uint32_t smem_to_u32(const void* p) {
    uint32_t a;
    asm("{ .reg .u64 t; cvta.to.shared.u64 t, %1; cvt.u32.u64 %0, t; }" : "=r"(a) : "l"(p));
    return a;
}
// pack two f32 -> bf16x2 (lo half = a, hi half = b)
__device__ __forceinline__ uint32_t pack_bf16(float a, float b) {
    uint32_t r;
    asm("cvt.rn.bf16x2.f32 %0, %1, %2;" : "=r"(r) : "f"(b), "f"(a));
    return r;
}
__device__ __forceinline__ float bflo(uint32_t u) { return __uint_as_float(u << 16); }
__device__ __forceinline__ float bfhi(uint32_t u) { return __uint_as_float(u & 0xffff0000u); }

// split f32x4 into bf16 hi + residual bf16 lo; store 8B each
__device__ __forceinline__ void split_store(float4 v, char* hp, char* lp) {
    uint32_t h01 = pack_bf16(v.x, v.y);
    uint32_t h23 = pack_bf16(v.z, v.w);
    float l0 = v.x - bflo(h01), l1 = v.y - bfhi(h01);
    float l2 = v.z - bflo(h23), l3 = v.w - bfhi(h23);
    uint32_t q01 = pack_bf16(l0, l1);
    uint32_t q23 = pack_bf16(l2, l3);
    *(uint2*)hp = make_uint2(h01, h23);
    *(uint2*)lp = make_uint2(q01, q23);
}

#define LDSM_X4(R, ADDR) \
    asm volatile("ldmatrix.sync.aligned.m8n8.x4.shared.b16 {%0,%1,%2,%3}, [%4];" \
        : "=r"((R)[0]), "=r"((R)[1]), "=r"((R)[2]), "=r"((R)[3]) : "r"(ADDR))

__device__ __forceinline__ void mma16816(float* d, const uint32_t* a, const uint32_t* b) {
    asm volatile("mma.sync.aligned.m16n8k16.row.col.f32.bf16.bf16.f32 "
        "{%0,%1,%2,%3}, {%4,%5,%6,%7}, {%8,%9}, {%0,%1,%2,%3};"
        : "+f"(d[0]), "+f"(d[1]), "+f"(d[2]), "+f"(d[3])
        : "r"(a[0]), "r"(a[1]), "r"(a[2]), "r"(a[3]), "r"(b[0]), "r"(b[1]));
}

__device__ __forceinline__ void red4(float* p, float4 v) {
    asm volatile("red.global.add.v4.f32 [%0], {%1,%2,%3,%4};"
                 :: "l"(p), "f"(v.x), "f"(v.y), "f"(v.z), "f"(v.w) : "memory");
}

// ---------------- zero fill --------------------------------------------------
__global__ __launch_bounds__(256) void k_zero(float4* p, int n4) {
    int i = blockIdx.x * 256 + threadIdx.x;
    if (i < n4) p[i] = make_float4(0.f, 0.f, 0.f, 0.f);
}

// ---------------- bf16x3 mma GEMM + fused bias + attention dots --------------
// smem: bias[256] @0, attA @1024, attB @2048, stages @3072
// stage: A_hi 128x32 bf16 pitch80 (10240B) | A_lo | B_hi 256x32 pitch80 (20480B) | B_lo
#define ROWB      80
#define SM_BIAS   0
#define SM_ATTA   1024
#define SM_ATTB   2048
#define SM_TILE   3072
#define ST_A_HI   0
#define ST_A_LO   10240
#define ST_B_HI   20480
#define ST_B_LO   40960
#define STAGE_BYTES 61440
#define SMEM_GEMM_TOTAL (SM_TILE + 2 * STAGE_BYTES)   // 125952

struct GemmArgs {
    const float* X; const float* W; const float* bias;
    float* H; const float* attA; const float* attB;
    float* outA; float* outB;
};

__global__ void __launch_bounds__(512, 1) k_gemm_mma(GemmArgs g0, GemmArgs g1)
{
    extern __shared__ char smem[];
    const GemmArgs g = blockIdx.y ? g1 : g0;
    const int t = threadIdx.x;
    const int lane = t & 31;
    const int wid = t >> 5;
    const int wm = wid >> 2;      // 0..3 -> rows wm*32
    const int wn = wid & 3;       // 0..3 -> cols wn*64
    const int rbase = blockIdx.x * MTILE;

    if (t < 256) {
        ((float*)(smem + SM_BIAS))[t] = g.bias[t];
        ((float*)(smem + SM_ATTA))[t] = g.attA[t];
        ((float*)(smem + SM_ATTB))[t] = g.attB[t];
    }

    float4 pa[2], pb[4];

#define LOAD_REGS(c) do { \
    for (int i = 0; i < 2; i++) { \
        int idx = t + 512 * i; int row = idx >> 3, f = idx & 7; \
        int gr = rbase + row; \
        pa[i] = (gr < NNODE) \
            ? *(const float4*)(g.X + (size_t)gr * CC + (c) * KC + f * 4) \
            : make_float4(0.f, 0.f, 0.f, 0.f); \
    } \
    for (int i = 0; i < 4; i++) { \
        int idx = t + 512 * i; int row = idx >> 3, f = idx & 7; \
        pb[i] = *(const float4*)(g.W + (size_t)row * CC + (c) * KC + f * 4); \
    } } while (0)

#define STORE_REGS(s) do { \
    char* base = smem + SM_TILE + (s) * STAGE_BYTES; \
    for (int i = 0; i < 2; i++) { \
        int idx = t + 512 * i; int row = idx >> 3, f = idx & 7; \
        split_store(pa[i], base + ST_A_HI + row * ROWB + f * 8, \
                           base + ST_A_LO + row * ROWB + f * 8); \
    } \
    for (int i = 0; i < 4; i++) { \
        int idx = t + 512 * i; int row = idx >> 3, f = idx & 7; \
        split_store(pb[i], base + ST_B_HI + row * ROWB + f * 8, \
                           base + ST_B_LO + row * ROWB + f * 8); \
    } } while (0)

    float acc[2][8][4];
#pragma unroll
    for (int a = 0; a < 2; a++)
#pragma unroll
        for (int b = 0; b < 8; b++)
#pragma unroll
            for (int k = 0; k < 4; k++) acc[a][b][k] = 0.f;

    LOAD_REGS(0);
    STORE_REGS(0);
    LOAD_REGS(1);

    const uint32_t sbase = smem_to_u32(smem) + SM_TILE;
    const uint32_t a_lane_off = (uint32_t)((lane & 15) * ROWB + (lane >> 4) * 16);
    const uint32_t b_lane_off = (uint32_t)(((lane & 7) + ((lane >> 4) & 1) * 8) * ROWB
                                           + ((lane >> 3) & 1) * 16);

    for (int c = 0; c < NCHUNK; c++) {
        const int b = c & 1;
        __syncthreads();                       // mma of chunk c-1 done everywhere
        if (c + 1 < NCHUNK) STORE_REGS(b ^ 1); // stage chunk c+1
        __syncthreads();                       // stage b (chunk c) visible
        if (c + 2 < NCHUNK) LOAD_REGS(c + 2);  // LDGs in flight under mma
        const uint32_t stg = sbase + (uint32_t)b * STAGE_BYTES;
#pragma unroll
        for (int ks = 0; ks < 2; ks++) {
            uint32_t ahi[2][4], alo[2][4];
            uint32_t a_base = stg + ST_A_HI + (uint32_t)(wm * 32 * ROWB) + ks * 32 + a_lane_off;
            LDSM_X4(ahi[0], a_base);
            LDSM_X4(ahi[1], a_base + 16 * ROWB);
            LDSM_X4(alo[0], a_base + (ST_A_LO - ST_A_HI));
            LDSM_X4(alo[1], a_base + (ST_A_LO - ST_A_HI) + 16 * ROWB);
            uint32_t b_base = stg + ST_B_HI + (uint32_t)(wn * 64 * ROWB) + ks * 32 + b_lane_off;
#pragma unroll
            for (int np = 0; np < 4; np++) {
                uint32_t bh[4], bl[4];
                LDSM_X4(bh, b_base + np * 16 * ROWB);
                LDSM_X4(bl, b_base + np * 16 * ROWB + (ST_B_LO - ST_B_HI));
#pragma unroll
                for (int mt = 0; mt < 2; mt++) {
                    mma16816(acc[mt][2 * np],     ahi[mt], bh);
                    mma16816(acc[mt][2 * np],     alo[mt], bh);
                    mma16816(acc[mt][2 * np],     ahi[mt], bl);
                    mma16816(acc[mt][2 * np + 1], ahi[mt], bh + 2);
                    mma16816(acc[mt][2 * np + 1], alo[mt], bh + 2);
                    mma16816(acc[mt][2 * np + 1], ahi[mt], bl + 2);
                }
            }
        }
    }

    // ---- epilogue: bias add, H store, attention dots (fused) ----
    const float* bias = (const float*)(smem + SM_BIAS);
    const float* aA = (const float*)(smem + SM_ATTA);
    const float* aB = (const float*)(smem + SM_ATTB);
    const int g4 = lane >> 2, q = lane & 3;
#pragma unroll
    for (int mt = 0; mt < 2; mt++) {
#pragma unroll
        for (int half = 0; half < 2; half++) {
            const int row = rbase + wm * 32 + mt * 16 + g4 + 8 * half;
            const bool ok = row < NNODE;
            float dA0 = 0.f, dA1 = 0.f, dB0 = 0.f, dB1 = 0.f;
#pragma unroll
            for (int nt = 0; nt < 8; nt++) {
                const int c0 = wn * 64 + nt * 8 + q * 2;
                float v0 = acc[mt][nt][2 * half + 0] + bias[c0];
                float v1 = acc[mt][nt][2 * half + 1] + bias[c0 + 1];
                if (ok) *(float2*)(g.H + (size_t)row * CC + c0) = make_float2(v0, v1);
                float da = v0 * aA[c0] + v1 * aA[c0 + 1];
                float db = v0 * aB[c0] + v1 * aB[c0 + 1];
                if (nt < 4) { dA0 += da; dB0 += db; }
                else        { dA1 += da; dB1 += db; }
            }
#pragma unroll
            for (int o = 1; o < 4; o <<= 1) {
                dA0 += __shfl_xor_sync(0xffffffffu, dA0, o);
                dA1 += __shfl_xor_sync(0xffffffffu, dA1, o);
                dB0 += __shfl_xor_sync(0xffffffffu, dB0, o);
                dB1 += __shfl_xor_sync(0xffffffffu, dB1, o);
            }
            if (q == 0 && ok) {
                const int hb = row * 8 + wn * 2;
                g.outA[hb]     = dA0;
                g.outA[hb + 1] = dA1;
                g.outB[hb]     = dB0;
                g.outB[hb + 1] = dB1;
            }
        }
    }
#undef LOAD_REGS
#undef STORE_REGS
}

// ---------------- fused edge pass: exp-logit, seg-sum, scatter ---------------
struct EdgeArgs {
    const int* eidx; const float* a_s; const float* a_d;
    const float* hsrc; float* sdst; float* acc;
};

__global__ __launch_bounds__(256) void k_edge2(EdgeArgs e0, EdgeArgs e1)
{
    const EdgeArgs E = blockIdx.y ? e1 : e0;
    int e = blockIdx.x * 8 + (threadIdx.x >> 5);
    int lane = threadIdx.x & 31;
    if (e >= NE) return;
    int src = E.eidx[e];
    int dst = E.eidx[NE + e];
    float ev = 0.f;
    if (lane < 8) {
        float l = E.a_s[src * 8 + lane] + E.a_d[dst * 8 + lane];
        l = (l > 0.f) ? l : 0.2f * l;
        ev = __expf(l);
        atomicAdd(&E.sdst[dst * 8 + lane], ev);
    }
    float w0 = __shfl_sync(0xffffffffu, ev, lane >> 3);
    float w1 = __shfl_sync(0xffffffffu, ev, 4 + (lane >> 3));
    const float4* hp = (const float4*)(E.hsrc + (size_t)src * CC);
    float4 m0 = hp[lane];
    float4 m1 = hp[lane + 32];
    m0.x *= w0; m0.y *= w0; m0.z *= w0; m0.w *= w0;
    m1.x *= w1; m1.y *= w1; m1.z *= w1; m1.w *= w1;
    float* dp = E.acc + (size_t)dst * CC + 4 * lane;
    red4(dp, m0);
    red4(dp + 128, m1);
}

// ---------------- finalize: divide by seg-sum, relu, BN partial sums ---------
__global__ __launch_bounds__(256) void k_finalize2(
    float* __restrict__ acc0, const float* __restrict__ s0,
    float* __restrict__ acc1, const float* __restrict__ s1)
{
    float* acc = blockIdx.y ? acc1 : acc0;
    const float* s = blockIdx.y ? s1 : s0;
    float* bnsum = g_bnsum + blockIdx.y * 512;
    const int q = threadIdx.x & 63;
    const int rl = threadIdx.x >> 6;
    const int row0 = blockIdx.x * 32;
    const int head = q >> 3;
    float4 sum = make_float4(0.f, 0.f, 0.f, 0.f);
    float4 sq  = make_float4(0.f, 0.f, 0.f, 0.f);
#pragma unroll
    for (int i = 0; i < 8; i++) {
        int r = row0 + i * 4 + rl;
        if (r < NNODE) {
            float inv = 1.f / (s[r * 8 + head] + 1e-16f);
            float4 v = *(float4*)(acc + (size_t)r * CC + 4 * q);
            v.x = fmaxf(v.x * inv, 0.f);
            v.y = fmaxf(v.y * inv, 0.f);
            v.z = fmaxf(v.z * inv, 0.f);
            v.w = fmaxf(v.w * inv, 0.f);
            *(float4*)(acc + (size_t)r * CC + 4 * q) = v;
            sum.x += v.x; sum.y += v.y; sum.z += v.z; sum.w += v.w;
            sq.x += v.x * v.x; sq.y += v.y * v.y; sq.z += v.z * v.z; sq.w += v.w * v.w;
        }
    }
    __shared__ float4 shs[256], shq[256];
    shs[threadIdx.x] = sum;
    shq[threadIdx.x] = sq;
    __syncthreads();
    if (threadIdx.x < 64) {
        float4 S = shs[threadIdx.x];
        float4 Q = shq[threadIdx.x];
#pragma unroll
        for (int k = 64; k < 256; k += 64) {
            float4 a = shs[threadIdx.x + k];
            float4 b = shq[threadIdx.x + k];
            S.x += a.x; S.y += a.y; S.z += a.z; S.w += a.w;
            Q.x += b.x; Q.y += b.y; Q.z += b.z; Q.w += b.w;
        }
        int c = 4 * threadIdx.x;
        atomicAdd(&bnsum[c + 0], S.x); atomicAdd(&bnsum[c + 1], S.y);
        atomicAdd(&bnsum[c + 2], S.z); atomicAdd(&bnsum[c + 3], S.w);
        atomicAdd(&bnsum[256 + c + 0], Q.x); atomicAdd(&bnsum[256 + c + 1], Q.y);
        atomicAdd(&bnsum[256 + c + 2], Q.z); atomicAdd(&bnsum[256 + c + 3], Q.w);
    }
}

// ---------------- BN stats -> per-channel affine -----------------------------
__global__ __launch_bounds__(512) void k_bnstats(
    const float* __restrict__ gamma, const float* __restrict__ beta)
{
    int t = threadIdx.x;
    int c = t & 255;
    int which = t >> 8;
    const float invN = 1.f / 100000.f;
    float mean = g_bnsum[which * 512 + c] * invN;
    float var  = g_bnsum[which * 512 + 256 + c] * invN - mean * mean;
    float scale = gamma[c] * rsqrtf(var + 1e-5f);
    g_bn[which * 512 + c]       = scale;
    g_bn[which * 512 + 256 + c] = beta[c] - mean * scale;
}

// ---------------- classifier: sigmoid(dot(BN(z_req[i]), BN(z_code[j]))) ------
__global__ __launch_bounds__(256) void k_classify(
    const int* __restrict__ eli, float* __restrict__ out)
{
    __shared__ float bn[1024];
    int t = threadIdx.x;
#pragma unroll
    for (int k = 0; k < 4; k++) bn[t + 256 * k] = g_bn[t + 256 * k];
    __syncthreads();
    int e = blockIdx.x * 8 + (t >> 5);
    int lane = t & 31;
    if (e >= NLAB) return;
    int i = eli[e];
    int j = eli[NLAB + e];
    const float4* zr = (const float4*)(g_acc_req + (size_t)i * CC);
    const float4* zc = (const float4*)(g_acc_code + (size_t)j * CC);
    float4 a0 = zr[lane], a1 = zr[lane + 32];
    float4 b0 = zc[lane], b1 = zc[lane + 32];
    int c0 = 4 * lane, c1 = 128 + 4 * lane;
    float dot = 0.f;
#pragma unroll
    for (int k = 0; k < 4; k++) {
        float ya = (&a0.x)[k] * bn[c0 + k] + bn[256 + c0 + k];
        float yb = (&b0.x)[k] * bn[512 + c0 + k] + bn[768 + c0 + k];
        dot += ya * yb;
    }
#pragma unroll
    for (int k = 0; k < 4; k++) {
        float ya = (&a1.x)[k] * bn[c1 + k] + bn[256 + c1 + k];
        float yb = (&b1.x)[k] * bn[512 + c1 + k] + bn[768 + c1 + k];
        dot += ya * yb;
    }
#pragma unroll
    for (int o = 16; o >= 1; o >>= 1) dot += __shfl_xor_sync(0xffffffffu, dot, o);
    if (lane == 0) out[e] = 1.f / (1.f + __expf(-dot));
}

// ---------------- host -------------------------------------------------------
template <class T>
static T* getsym(const void* sym) {
    void* p = nullptr;
    cudaGetSymbolAddress(&p, sym);
    return (T*)p;
}

extern "C" void kernel_launch(void* const* d_in, const int* in_sizes, int n_in,
                              void* d_out, int out_size)
{
    const float* x_req      = (const float*)d_in[0];
    const float* x_code     = (const float*)d_in[1];
    const int*   e_rc       = (const int*)d_in[2];
    const int*   e_cr       = (const int*)d_in[3];
    const int*   eli        = (const int*)d_in[4];
    const float* W_req      = (const float*)d_in[5];
    const float* b_req      = (const float*)d_in[6];
    const float* W_code     = (const float*)d_in[7];
    const float* b_code     = (const float*)d_in[8];
    const float* att_src_rc = (const float*)d_in[9];
    const float* att_dst_rc = (const float*)d_in[10];
    const float* att_src_cr = (const float*)d_in[11];
    const float* att_dst_cr = (const float*)d_in[12];
    // d_in[13..15] (k_W, k_b, q) are dead: semantic attention over one metapath.
    const float* gamma      = (const float*)d_in[16];
    const float* beta       = (const float*)d_in[17];
    float* out = (float*)d_out;

    float* h_req    = getsym<float>(g_h_req);
    float* h_code   = getsym<float>(g_h_code);
    float* acc_req  = getsym<float>(g_acc_req);
    float* acc_code = getsym<float>(g_acc_code);
    float* as_rc    = getsym<float>(g_as_rc);
    float* ad_rc    = getsym<float>(g_ad_rc);
    float* as_cr    = getsym<float>(g_as_cr);
    float* ad_cr    = getsym<float>(g_ad_cr);
    float* s_req    = getsym<float>(g_s_req);
    float* s_code   = getsym<float>(g_s_code);
    float* bnsum    = getsym<float>(g_bnsum);

    const int accN4 = NNODE * CC / 4;
    k_zero<<<(accN4 + 255) / 256, 256>>>((float4*)acc_req, accN4);
    k_zero<<<(accN4 + 255) / 256, 256>>>((float4*)acc_code, accN4);
    const int sN4 = NNODE * HEADS / 4;
    k_zero<<<(sN4 + 255) / 256, 256>>>((float4*)s_req, sN4);
    k_zero<<<(sN4 + 255) / 256, 256>>>((float4*)s_code, sN4);
    k_zero<<<1, 256>>>((float4*)bnsum, 256);

    // ---- bf16x3 tensor-core projections + fused attention dots ----
    GemmArgs gr{ x_req,  W_req,  b_req,  h_req,  att_src_rc, att_dst_cr, as_rc, ad_cr };
    GemmArgs gc{ x_code, W_code, b_code, h_code, att_dst_rc, att_src_cr, ad_rc, as_cr };
    cudaFuncSetAttribute(k_gemm_mma, cudaFuncAttributeMaxDynamicSharedMemorySize,
                         SMEM_GEMM_TOTAL);
    dim3 ggrid((NNODE + MTILE - 1) / MTILE, 2);
    k_gemm_mma<<<ggrid, 512, SMEM_GEMM_TOTAL>>>(gr, gc);

    // ---- fused edge passes ----
    EdgeArgs er{ e_rc, as_rc, ad_rc, h_req,  s_code, acc_code };
    EdgeArgs ec{ e_cr, as_cr, ad_cr, h_code, s_req,  acc_req  };
    dim3 egrid((NE + 7) / 8, 2);
    k_edge2<<<egrid, 256>>>(er, ec);

    // ---- finalize (divide, relu, BN partials) ----
    dim3 fgrid(NNODE / 32, 2);
    k_finalize2<<<fgrid, 256>>>(acc_req, s_req, acc_code, s_code);

    k_bnstats<<<1, 512>>>(gamma, beta);

    k_classify<<<(NLAB + 7) / 8, 256>>>(eli, out);
}